// round 1
// baseline (speedup 1.0000x reference)
#include <cuda_runtime.h>
#include <math.h>

#define B 128
#define N 996
#define BN (B*N)
#define DIM 16
#define QKD 128
#define GSZ 256
#define NG 4
#define DEPTH 8
#define VOC 1024
#define ROTD 32
#define QSTR 132   // padded smem row stride (floats) for 128-dim rows

// ---------------- scratch (device globals; allocation-free) ----------------
__device__ __align__(16) float g_x[BN*DIM];        // activations (residual stream)
__device__ __align__(16) float g_qk[BN*QKD];       // silu(normed @ Wqk + bqk)
__device__ __align__(16) float g_v[BN*32];
__device__ __align__(16) float g_gate[BN*32];
__device__ __align__(16) float g_qo[BN*32];        // quadratic attention out
__device__ __align__(16) float g_linkv[B*QKD*32];  // per-batch linear KV state
__device__ float g_hmax[BN];                       // max-logit per token

// log(10000)/16 (rotary), log(10000)/8 (pos enc)
#define ROT_LC 0.57564627324851142
#define POS_LC 1.1512925464970228

// ---------------- helpers ----------------
__device__ __forceinline__ float siluf(float a) {
    return a / (1.0f + __expf(-a) * 0.0f + expf(-a) * 1.0f - 0.0f); // keep accurate expf
}
__device__ __forceinline__ float silu_acc(float a) { return a / (1.0f + expf(-a)); }

// gamma/beta + rotary on a 4-wide chunk starting at dim d (d % 4 == 0)
__device__ __forceinline__ float4 qk_xform(float4 qv, int d, int pos,
                                           const float* __restrict__ gam,
                                           const float* __restrict__ bet,
                                           const float* __restrict__ frq) {
    float v0 = qv.x * gam[d]   + bet[d];
    float v1 = qv.y * gam[d+1] + bet[d+1];
    float v2 = qv.z * gam[d+2] + bet[d+2];
    float v3 = qv.w * gam[d+3] + bet[d+3];
    if (d < ROTD) {
        float s, c;
        sincosf((float)pos * frq[d >> 1], &s, &c);
        float a0 = v0 * c - v1 * s;
        float a1 = v1 * c + v0 * s;
        sincosf((float)pos * frq[(d >> 1) + 1], &s, &c);
        float a2 = v2 * c - v3 * s;
        float a3 = v3 * c + v2 * s;
        v0 = a0; v1 = a1; v2 = a2; v3 = a3;
    }
    return make_float4(v0, v1, v2, v3);
}

// ---------------- K0: embedding + positional encoding ----------------
__global__ void k_embed(const int* __restrict__ kmer, const float* __restrict__ emb,
                        const float* __restrict__ ps) {
    int idx = blockIdx.x * blockDim.x + threadIdx.x;
    if (idx >= BN * DIM) return;
    int d = idx & 15;
    int tok = idx >> 4;
    int t = tok % N;
    int vtok = kmer[tok];
    int j = (d < 8) ? d : d - 8;
    float inv = (float)exp(-(double)j * POS_LC);
    float ang = (float)t * inv;
    float p = (d < 8) ? sinf(ang) : cosf(ang);
    g_x[idx] = emb[vtok * DIM + d] + p * ps[0];
}

// ---------------- K1: norm + shift + projections (16 tokens / CTA) ----------------
__global__ void k_proj(const float* __restrict__ ng,
                       const float* __restrict__ Wh, const float* __restrict__ bh,
                       const float* __restrict__ Wqk, const float* __restrict__ bqk) {
    __shared__ float sWh[16*64];
    __shared__ float sWqk[16*128];
    __shared__ float sbh[64];
    __shared__ float sbqk[128];
    __shared__ float xr[17][16];   // row r <-> flat token base-1+r
    __shared__ float scl[17];
    __shared__ float nm[16][16];
    int tid = threadIdx.x;
    long base = (long)blockIdx.x * 16;

    for (int i = tid; i < 16*64; i += 256) sWh[i] = Wh[i];
    for (int i = tid; i < 16*128; i += 256) sWqk[i] = Wqk[i];
    if (tid < 64) sbh[tid] = bh[tid];
    if (tid < 128) sbqk[tid] = bqk[tid];
    for (int i = tid; i < 17*16; i += 256) {
        int r = i >> 4, d = i & 15;
        long f = base - 1 + r;
        xr[r][d] = (f >= 0) ? g_x[f * DIM + d] : 0.0f;
    }
    __syncthreads();
    if (tid < 17) {
        float s = 0.0f;
        #pragma unroll
        for (int d = 0; d < 16; d++) s += xr[tid][d] * xr[tid][d];
        float nrm = sqrtf(s) * 0.25f;
        scl[tid] = ng[0] / fmaxf(nrm, 1e-5f);
    }
    __syncthreads();
    {   // normed: first 8 dims from shifted (previous token's normalized), last 8 from self
        int i = tid >> 4, d = tid & 15;
        long flat = base + i;
        float val;
        if (d < 8) {
            val = ((flat % N) == 0) ? 0.0f : xr[i][d] * scl[i];
        } else {
            val = xr[i+1][d] * scl[i+1];
        }
        nm[i][d] = val;
    }
    __syncthreads();
    for (int o = tid; o < 16 * 192; o += 256) {
        int i = o / 192, u = o % 192;
        float acc;
        if (u < 64) {
            acc = sbh[u];
            #pragma unroll
            for (int d = 0; d < 16; d++) acc += nm[i][d] * sWh[d * 64 + u];
        } else {
            int q = u - 64;
            acc = sbqk[q];
            #pragma unroll
            for (int d = 0; d < 16; d++) acc += nm[i][d] * sWqk[d * 128 + q];
        }
        float s = silu_acc(acc);
        long flat = base + i;
        if (u < 32)       g_v[flat * 32 + u] = s;
        else if (u < 64)  g_gate[flat * 32 + (u - 32)] = s;
        else              g_qk[flat * 128 + (u - 64)] = s;
    }
}

// ---------------- K2: quadratic attention (grid: 2 x 4 x B) ----------------
// smem: Qs[128][132] + Ks[32][132] + As[128][33] + Vs[32][32] + frq[16]
#define ATTN_SMEM ((128*QSTR + 32*QSTR + 128*33 + 32*32 + 16) * 4)
__global__ void __launch_bounds__(256, 2)
k_attn(const float* __restrict__ gamma, const float* __restrict__ beta) {
    extern __shared__ float sm[];
    float* Qs = sm;
    float* Ks = Qs + 128 * QSTR;
    float* As = Ks + 32 * QSTR;
    float* Vs = As + 128 * 33;
    float* frq = Vs + 32 * 32;
    int tid = threadIdx.x;
    int b = blockIdx.z, g = blockIdx.y, qh = blockIdx.x;
    if (tid < 16) frq[tid] = (float)exp(-(double)tid * ROT_LC);
    __syncthreads();

    const float* gq = gamma;            // row 0 = quad_q
    const float* bq = beta;
    const float* gk = gamma + 2 * QKD;  // row 2 = quad_k
    const float* bk = beta + 2 * QKD;

    {   // load + transform Q tile (128 rows x 128 dims)
        int row = tid >> 1;
        int d0 = (tid & 1) * 64;
        int pos = g * GSZ + qh * 128 + row;
        long src = ((long)b * N + pos) * QKD;
        for (int d = d0; d < d0 + 64; d += 4) {
            float4 qv = (pos < N) ? *(const float4*)&g_qk[src + d]
                                  : make_float4(0, 0, 0, 0);
            float4 r = qk_xform(qv, d, pos, gq, bq, frq);
            float* dst = &Qs[row * QSTR + d];
            dst[0] = r.x; dst[1] = r.y; dst[2] = r.z; dst[3] = r.w;
        }
    }

    float oacc[16];
    #pragma unroll
    for (int e = 0; e < 16; e++) oacc[e] = 0.0f;
    int oi = tid >> 1;
    int eh = (tid & 1) * 16;

    for (int kc = 0; kc < 8; kc++) {
        __syncthreads();   // protects Q-load (first iter) and prior stage-B reads
        {   // load + transform K chunk (32 keys) and V chunk
            int row = tid >> 3;
            int d0 = (tid & 7) * 16;
            int pos = g * GSZ + kc * 32 + row;
            long src = ((long)b * N + pos) * QKD;
            for (int d = d0; d < d0 + 16; d += 4) {
                float4 qv = (pos < N) ? *(const float4*)&g_qk[src + d]
                                      : make_float4(0, 0, 0, 0);
                float4 r = qk_xform(qv, d, pos, gk, bk, frq);
                float* dst = &Ks[row * QSTR + d];
                dst[0] = r.x; dst[1] = r.y; dst[2] = r.z; dst[3] = r.w;
            }
            int e0 = (tid & 7) * 4;
            float4 vv = (pos < N) ? *(const float4*)&g_v[((long)b * N + pos) * 32 + e0]
                                  : make_float4(0, 0, 0, 0);
            *(float4*)&Vs[row * 32 + e0] = vv;
        }
        __syncthreads();
        {   // stage A: sim chunk -> relu^2 -> As
            int ti = tid >> 3;      // base query row (rows ti, ti+32, ti+64, ti+96)
            int tj = tid & 7;       // base key col  (cols tj, tj+8, tj+16, tj+24)
            float acc[4][4];
            #pragma unroll
            for (int a = 0; a < 4; a++)
                #pragma unroll
                for (int c = 0; c < 4; c++) acc[a][c] = 0.0f;
            #pragma unroll 8
            for (int kk = 0; kk < 128; kk += 4) {
                float4 q[4], kv[4];
                #pragma unroll
                for (int a = 0; a < 4; a++)
                    q[a] = *(const float4*)&Qs[(ti + 32 * a) * QSTR + kk];
                #pragma unroll
                for (int c = 0; c < 4; c++)
                    kv[c] = *(const float4*)&Ks[(tj + 8 * c) * QSTR + kk];
                #pragma unroll
                for (int a = 0; a < 4; a++)
                    #pragma unroll
                    for (int c = 0; c < 4; c++)
                        acc[a][c] += q[a].x * kv[c].x + q[a].y * kv[c].y
                                   + q[a].z * kv[c].z + q[a].w * kv[c].w;
            }
            #pragma unroll
            for (int a = 0; a < 4; a++) {
                #pragma unroll
                for (int c = 0; c < 4; c++) {
                    int col = tj + 8 * c;
                    int kpos = g * GSZ + kc * 32 + col;
                    float s = acc[a][c] * (1.0f / 256.0f);
                    s = fmaxf(s, 0.0f);
                    s = s * s;
                    if (kpos >= N) s = 0.0f;
                    As[(ti + 32 * a) * 33 + col] = s;
                }
            }
        }
        __syncthreads();
        // stage B: O += A_chunk * V_chunk
        #pragma unroll 4
        for (int j = 0; j < 32; j++) {
            float aij = As[oi * 33 + j];
            const float4* vp = (const float4*)&Vs[j * 32 + eh];
            float4 v0 = vp[0], v1 = vp[1], v2 = vp[2], v3 = vp[3];
            oacc[0]  += aij * v0.x; oacc[1]  += aij * v0.y;
            oacc[2]  += aij * v0.z; oacc[3]  += aij * v0.w;
            oacc[4]  += aij * v1.x; oacc[5]  += aij * v1.y;
            oacc[6]  += aij * v1.z; oacc[7]  += aij * v1.w;
            oacc[8]  += aij * v2.x; oacc[9]  += aij * v2.y;
            oacc[10] += aij * v2.z; oacc[11] += aij * v2.w;
            oacc[12] += aij * v3.x; oacc[13] += aij * v3.y;
            oacc[14] += aij * v3.z; oacc[15] += aij * v3.w;
        }
    }
    int qpos = g * GSZ + qh * 128 + oi;
    if (qpos < N) {
        float* dst = &g_qo[((long)b * N + qpos) * 32 + eh];
        #pragma unroll
        for (int e = 0; e < 16; e += 4)
            *(float4*)&dst[e] = make_float4(oacc[e], oacc[e+1], oacc[e+2], oacc[e+3]);
    }
}

// ---------------- K3: linear attention KV state (grid: B) ----------------
__global__ void k_linkv(const float* __restrict__ gamma, const float* __restrict__ beta) {
    __shared__ float lk[8][128];
    __shared__ float vsm[8][32];
    __shared__ float frq[16];
    int tid = threadIdx.x;
    int b = blockIdx.x;
    if (tid < 16) frq[tid] = (float)exp(-(double)tid * ROT_LC);

    const float* gl = gamma + 3 * QKD;  // row 3 = lin_k
    const float* bl = beta + 3 * QKD;
    float acc[16];
    #pragma unroll
    for (int e = 0; e < 16; e++) acc[e] = 0.0f;
    int dd = tid & 127;
    int e0 = (tid >> 7) * 16;

    for (int p0 = 0; p0 < N; p0 += 8) {
        __syncthreads();
        {
            int r = tid >> 5;
            int d0 = (tid & 31) * 4;
            int pos = p0 + r;
            if (pos < N) {
                float4 qv = *(const float4*)&g_qk[((long)b * N + pos) * QKD + d0];
                float4 rr = qk_xform(qv, d0, pos, gl, bl, frq);
                lk[r][d0] = rr.x; lk[r][d0+1] = rr.y; lk[r][d0+2] = rr.z; lk[r][d0+3] = rr.w;
            } else {
                lk[r][d0] = 0.0f; lk[r][d0+1] = 0.0f; lk[r][d0+2] = 0.0f; lk[r][d0+3] = 0.0f;
            }
            int r2 = tid >> 5, e = tid & 31;
            int pos2 = p0 + r2;
            vsm[r2][e] = (pos2 < N) ? g_v[((long)b * N + pos2) * 32 + e] : 0.0f;
        }
        __syncthreads();
        #pragma unroll
        for (int r = 0; r < 8; r++) {
            float lv = lk[r][dd];
            #pragma unroll
            for (int e = 0; e < 16; e++) acc[e] += lv * vsm[r][e0 + e];
        }
    }
    const float inv_n = 1.0f / (float)N;
    #pragma unroll
    for (int e = 0; e < 16; e++)
        g_linkv[((long)b * QKD + dd) * 32 + e0 + e] = acc[e] * inv_n;
}

// ---------------- K4: lin_out + gate + Wo + residual (warp per token) ----------------
__global__ void k_out(const float* __restrict__ gamma, const float* __restrict__ beta,
                      const float* __restrict__ Wo, const float* __restrict__ bo) {
    __shared__ float lq[8][128];
    __shared__ float ov[8][32];
    __shared__ float frq[16];
    int tid = threadIdx.x;
    int w = tid >> 5, lane = tid & 31;
    if (tid < 16) frq[tid] = (float)exp(-(double)tid * ROT_LC);
    __syncthreads();

    long tok = (long)blockIdx.x * 8 + w;
    int b = (int)(tok / N);
    int pos = (int)(tok % N);
    const float* gl = gamma + 1 * QKD;  // row 1 = lin_q
    const float* bl = beta + 1 * QKD;
    {
        int d0 = lane * 4;
        float4 qv = *(const float4*)&g_qk[tok * QKD + d0];
        float4 rr = qk_xform(qv, d0, pos, gl, bl, frq);
        lq[w][d0] = rr.x; lq[w][d0+1] = rr.y; lq[w][d0+2] = rr.z; lq[w][d0+3] = rr.w;
    }
    __syncwarp();
    float acc = g_qo[tok * 32 + lane];
    const float* kv = &g_linkv[(long)b * QKD * 32];
    #pragma unroll 8
    for (int d = 0; d < 128; d++) acc += lq[w][d] * kv[d * 32 + lane];
    acc *= g_gate[tok * 32 + lane];
    ov[w][lane] = acc;
    __syncwarp();
    if (lane < 16) {
        float y = bo[lane];
        #pragma unroll
        for (int e = 0; e < 32; e++) y += ov[w][e] * Wo[e * DIM + lane];
        g_x[tok * DIM + lane] += y;
    }
}

// ---------------- K5: final norm + logits + vocab max (16 tokens / CTA) ----------------
#define LOGITS_SMEM ((16*1024 + 1024 + 16*16) * 4)
__global__ void k_logits(const float* __restrict__ fg, const float* __restrict__ Wl,
                         const float* __restrict__ blv) {
    extern __shared__ float sm[];
    float* sW = sm;              // [16][1024]
    float* sb = sW + 16 * 1024;  // [1024]
    float* xn = sb + 1024;       // [16][16]
    __shared__ float wred[8];
    __shared__ float xs[16];
    int tid = threadIdx.x;
    long base = (long)blockIdx.x * 16;

    for (int i = tid; i < (16 * 1024) / 4; i += 256)
        ((float4*)sW)[i] = ((const float4*)Wl)[i];
    for (int i = tid; i < 1024; i += 256) sb[i] = blv[i];
    {
        int tt = tid >> 4, d = tid & 15;
        xn[tt * 16 + d] = g_x[(base + tt) * DIM + d];
    }
    __syncthreads();
    if (tid < 16) {
        float s = 0.0f;
        #pragma unroll
        for (int d = 0; d < 16; d++) { float v = xn[tid * 16 + d]; s += v * v; }
        xs[tid] = fg[0] / fmaxf(sqrtf(s) * 0.25f, 1e-5f);
    }
    __syncthreads();
    {
        int tt = tid >> 4, d = tid & 15;
        xn[tt * 16 + d] *= xs[tt];
    }
    __syncthreads();
    int warp = tid >> 5, lane = tid & 31;
    int v0 = tid * 4;
    for (int tt = 0; tt < 16; tt++) {
        float s0 = sb[v0], s1 = sb[v0 + 1], s2 = sb[v0 + 2], s3 = sb[v0 + 3];
        #pragma unroll
        for (int d = 0; d < 16; d++) {
            float xv = xn[tt * 16 + d];
            float4 wv = *(const float4*)&sW[d * 1024 + v0];
            s0 += xv * wv.x; s1 += xv * wv.y; s2 += xv * wv.z; s3 += xv * wv.w;
        }
        float m = fmaxf(fmaxf(s0, s1), fmaxf(s2, s3));
        #pragma unroll
        for (int off = 16; off > 0; off >>= 1)
            m = fmaxf(m, __shfl_xor_sync(0xffffffff, m, off));
        if (lane == 0) wred[warp] = m;
        __syncthreads();
        if (tid == 0) {
            float mm = wred[0];
            #pragma unroll
            for (int j = 1; j < 8; j++) mm = fmaxf(mm, wred[j]);
            g_hmax[base + tt] = mm;
        }
        __syncthreads();
    }
}

// ---------------- K6: head MLP (grid: B) ----------------
__global__ void k_head(const float* __restrict__ W1, const float* __restrict__ b1,
                       const float* __restrict__ W2, const float* __restrict__ b2,
                       float* __restrict__ out) {
    __shared__ float red[8][32];
    __shared__ float rr[32];
    int tid = threadIdx.x;
    int b = blockIdx.x;
    int col = tid & 31, seg = tid >> 5;
    float acc = 0.0f;
    int t0 = seg * 125;
    int t1 = min(t0 + 125, N);
    for (int t = t0; t < t1; t++)
        acc += g_hmax[(long)b * N + t] * W1[t * 32 + col];
    red[seg][col] = acc;
    __syncthreads();
    if (tid < 32) {
        float s = b1[tid];
        #pragma unroll
        for (int k = 0; k < 8; k++) s += red[k][tid];
        rr[tid] = fmaxf(s, 0.0f);
    }
    __syncthreads();
    if (tid == 0) {
        float o = b2[0];
        #pragma unroll
        for (int j = 0; j < 32; j++) o += rr[j] * W2[j];
        out[b] = o;
    }
}

// ---------------- launch ----------------
extern "C" void kernel_launch(void* const* d_in, const int* in_sizes, int n_in,
                              void* d_out, int out_size) {
    const int*   kmer    = (const int*)  d_in[0];
    const float* emb     = (const float*)d_in[1];
    const float* psc     = (const float*)d_in[2];
    const float* norm_g  = (const float*)d_in[3];
    const float* Wh      = (const float*)d_in[4];
    const float* bh      = (const float*)d_in[5];
    const float* Wqk     = (const float*)d_in[6];
    const float* bqk     = (const float*)d_in[7];
    const float* gamma   = (const float*)d_in[8];
    const float* beta    = (const float*)d_in[9];
    const float* Wo      = (const float*)d_in[10];
    const float* bo      = (const float*)d_in[11];
    const float* fg      = (const float*)d_in[12];
    const float* Wl      = (const float*)d_in[13];
    const float* bl      = (const float*)d_in[14];
    const float* W1      = (const float*)d_in[15];
    const float* b1      = (const float*)d_in[16];
    const float* W2      = (const float*)d_in[17];
    const float* b2      = (const float*)d_in[18];
    float* out = (float*)d_out;

    cudaFuncSetAttribute(k_attn,   cudaFuncAttributeMaxDynamicSharedMemorySize, ATTN_SMEM);
    cudaFuncSetAttribute(k_logits, cudaFuncAttributeMaxDynamicSharedMemorySize, LOGITS_SMEM);

    k_embed<<<(BN * DIM + 255) / 256, 256>>>(kmer, emb, psc);

    for (int l = 0; l < DEPTH; l++) {
        const float* gm = gamma + (long)l * 4 * QKD;
        const float* bt = beta  + (long)l * 4 * QKD;
        k_proj<<<BN / 16, 256>>>(norm_g + l,
                                 Wh + (long)l * 16 * 64, bh + (long)l * 64,
                                 Wqk + (long)l * 16 * 128, bqk + (long)l * 128);
        k_attn<<<dim3(2, NG, B), 256, ATTN_SMEM>>>(gm, bt);
        k_linkv<<<B, 256>>>(gm, bt);
        k_out<<<BN / 8, 256>>>(gm, bt, Wo + (long)l * 32 * 16, bo + (long)l * 16);
    }

    k_logits<<<BN / 16, 256, LOGITS_SMEM>>>(fg, Wl, bl);
    k_head<<<B, 256>>>(W1, b1, W2, b2, out);
    (void)in_sizes; (void)n_in; (void)out_size;
}

// round 2
// speedup vs baseline: 1.0736x; 1.0736x over previous
#include <cuda_runtime.h>
#include <math.h>

#define B 128
#define N 996
#define BN (B*N)
#define DIM 16
#define QKD 128
#define GSZ 256
#define NG 4
#define DEPTH 8
#define VOC 1024
#define ROTD 32

#define QS_STR 132
#define KT_STR 132
#define AS_STR 130

// ---------------- scratch (device globals; allocation-free) ----------------
__device__ __align__(16) float g_x[BN*DIM];
__device__ __align__(16) float g_v[BN*32];
__device__ __align__(16) float g_gate[BN*32];
__device__ __align__(16) float g_qo[BN*32];
__device__ __align__(16) float g_qq[BN*QKD];     // transformed quad_q
__device__ __align__(16) float g_kk[BN*QKD];     // transformed quad_k
__device__ __align__(16) float g_lq[BN*QKD];     // transformed lin_q
__device__ __align__(16) float g_lk[BN*QKD];     // transformed lin_k
__device__ __align__(16) float g_linkvp[B*8*QKD*32]; // partial lin KV
__device__ __align__(16) float g_linkv[B*QKD*32];
__device__ float g_rc[N*16];                     // rotary cos table
__device__ float g_rs[N*16];                     // rotary sin table
__device__ float g_hmax[BN];

#define ROT_LC 0.57564627324851142   // ln(10000)/16
#define POS_LC 1.1512925464970228    // ln(10000)/8

// ---------------- f32x2 helpers (Blackwell packed fp32 FMA) ----------------
__device__ __forceinline__ unsigned long long pk2(float a, float b) {
    unsigned long long r;
    asm("mov.b64 %0,{%1,%2};" : "=l"(r) : "f"(a), "f"(b));
    return r;
}
__device__ __forceinline__ void fma2(unsigned long long& d,
                                     unsigned long long a, unsigned long long b) {
    asm("fma.rn.f32x2 %0,%1,%2,%0;" : "+l"(d) : "l"(a), "l"(b));
}
__device__ __forceinline__ float2 up2(unsigned long long v) {
    float2 f;
    asm("mov.b64 {%0,%1},%2;" : "=f"(f.x), "=f"(f.y) : "l"(v));
    return f;
}

__device__ __forceinline__ float silu_f(float a) {
    return __fdividef(a, 1.0f + __expf(-a));
}

// ---------------- K0: embedding + positional encoding ----------------
__global__ void k_embed(const int* __restrict__ kmer, const float* __restrict__ emb,
                        const float* __restrict__ ps) {
    int idx = blockIdx.x * blockDim.x + threadIdx.x;
    if (idx >= BN * DIM) return;
    int d = idx & 15;
    int tok = idx >> 4;
    int t = tok % N;
    int vtok = kmer[tok];
    int j = (d < 8) ? d : d - 8;
    float inv = (float)exp(-(double)j * POS_LC);
    float ang = (float)t * inv;
    float p = (d < 8) ? sinf(ang) : cosf(ang);
    g_x[idx] = emb[vtok * DIM + d] + p * ps[0];
}

// ---------------- K0b: rotary tables ----------------
__global__ void k_rot() {
    int idx = blockIdx.x * blockDim.x + threadIdx.x;
    if (idx >= N * 16) return;
    int t = idx >> 4, j = idx & 15;
    float inv = (float)exp(-(double)j * ROT_LC);
    float ang = (float)t * inv;
    g_rc[idx] = cosf(ang);
    g_rs[idx] = sinf(ang);
}

// ---------------- K1: norm + shift + projections + qk transforms ----------------
__global__ void k_proj(const float* __restrict__ ng,
                       const float* __restrict__ Wh, const float* __restrict__ bh,
                       const float* __restrict__ Wqk, const float* __restrict__ bqk,
                       const float* __restrict__ gamma, const float* __restrict__ beta) {
    __shared__ float sWh[16*64];
    __shared__ float sWqk[16*128];
    __shared__ float sbh[64];
    __shared__ float sbqk[128];
    __shared__ float xr[17][16];
    __shared__ float scl[17];
    __shared__ float nm[16][16];
    __shared__ float sqk[16][128];
    __shared__ float sg[4*128], sb2[4*128];
    __shared__ float sc[16][16], ss[16][16];
    int tid = threadIdx.x;
    int base = blockIdx.x * 16;

    for (int i = tid; i < 16*64; i += 256) sWh[i] = Wh[i];
    for (int i = tid; i < 16*128; i += 256) sWqk[i] = Wqk[i];
    if (tid < 64) sbh[tid] = bh[tid];
    if (tid < 128) sbqk[tid] = bqk[tid];
    for (int i = tid; i < 512; i += 256) { sg[i] = gamma[i]; sb2[i] = beta[i]; }
    for (int i = tid; i < 17*16; i += 256) {
        int r = i >> 4, d = i & 15;
        int f = base - 1 + r;
        xr[r][d] = (f >= 0) ? g_x[f * DIM + d] : 0.0f;
    }
    {   int i = tid >> 4, jj = tid & 15;
        int pos = (base + i) % N;
        sc[i][jj] = g_rc[pos * 16 + jj];
        ss[i][jj] = g_rs[pos * 16 + jj];
    }
    __syncthreads();
    if (tid < 17) {
        float s = 0.0f;
        #pragma unroll
        for (int d = 0; d < 16; d++) s += xr[tid][d] * xr[tid][d];
        scl[tid] = ng[0] / fmaxf(sqrtf(s) * 0.25f, 1e-5f);
    }
    __syncthreads();
    {   int i = tid >> 4, d = tid & 15;
        int flat = base + i;
        float val;
        if (d < 8) val = ((flat % N) == 0) ? 0.0f : xr[i][d] * scl[i];
        else       val = xr[i+1][d] * scl[i+1];
        nm[i][d] = val;
    }
    __syncthreads();
    for (int o = tid; o < 16 * 192; o += 256) {
        int i = o / 192, u = o % 192;
        float acc;
        if (u < 64) {
            acc = sbh[u];
            #pragma unroll
            for (int d = 0; d < 16; d++) acc += nm[i][d] * sWh[d * 64 + u];
        } else {
            int q = u - 64;
            acc = sbqk[q];
            #pragma unroll
            for (int d = 0; d < 16; d++) acc += nm[i][d] * sWqk[d * 128 + q];
        }
        float sv2 = silu_f(acc);
        int flat = base + i;
        if (u < 32)       g_v[flat * 32 + u] = sv2;
        else if (u < 64)  g_gate[flat * 32 + (u - 32)] = sv2;
        else              sqk[i][u - 64] = sv2;
    }
    __syncthreads();
    {   // apply gamma/beta + rotary, write 4 transformed tensors
        int i = tid >> 4;
        int d0 = (tid & 15) * 8;
        int flat = base + i;
        #pragma unroll
        for (int r = 0; r < 4; r++) {
            float* dst = (r == 0) ? g_qq : (r == 1) ? g_lq : (r == 2) ? g_kk : g_lk;
            #pragma unroll
            for (int dd = 0; dd < 8; dd += 2) {
                int d = d0 + dd;
                float v0 = sqk[i][d]   * sg[r*128 + d]   + sb2[r*128 + d];
                float v1 = sqk[i][d+1] * sg[r*128 + d+1] + sb2[r*128 + d+1];
                if (d0 < ROTD) {
                    float c = sc[i][d >> 1], s = ss[i][d >> 1];
                    float t0 = v0 * c - v1 * s;
                    v1 = v1 * c + v0 * s;
                    v0 = t0;
                }
                *(float2*)&dst[flat * QKD + d] = make_float2(v0, v1);
            }
        }
    }
}

// ---------------- K2: quadratic attention (grid: 2 x 4 x B) ----------------
#define ATTN_SMEM ((128*QS_STR + 128*KT_STR + 128*AS_STR + 128*32) * 4)
__global__ void __launch_bounds__(256, 1) k_attn() {
    extern __shared__ float sm[];
    float* Qs = sm;                       // [128][QS_STR]  (row-major, fp32)
    float* Kt = Qs + 128 * QS_STR;        // [kk][col] transposed K chunk
    float* As = Kt + 128 * KT_STR;        // [128][AS_STR] relu^2 weights
    float* Vs = As + 128 * AS_STR;        // [128][32]
    int tid = threadIdx.x;
    int b = blockIdx.z, g = blockIdx.y, qh = blockIdx.x;
    int tx = tid & 15, ty = tid >> 4;
    const int bN = b * N;

    {   // load Q tile (pretransformed)
        int row = tid >> 1;
        int d0 = (tid & 1) * 64;
        int pos = g * GSZ + qh * 128 + row;
        const float4* src = (const float4*)&g_qq[(long)(bN + pos) * QKD];
        #pragma unroll
        for (int d = 0; d < 64; d += 4) {
            float4 v = (pos < N) ? src[(d0 + d) >> 2] : make_float4(0,0,0,0);
            *(float4*)&Qs[row * QS_STR + d0 + d] = v;
        }
    }

    unsigned long long oacc[8];
    #pragma unroll
    for (int e = 0; e < 8; e++) oacc[e] = 0ull;
    int oi = tid >> 1, eh = (tid & 1) * 16;

    for (int kc = 0; kc < 2; kc++) {
        __syncthreads();
        {   // K chunk transposed + V chunk
            int col = tid & 127;
            int d0 = (tid >> 7) * 64;
            int pos = g * GSZ + kc * 128 + col;
            const float4* src = (const float4*)&g_kk[(long)(bN + pos) * QKD];
            #pragma unroll
            for (int d = 0; d < 64; d += 4) {
                float4 v = (pos < N) ? src[(d0 + d) >> 2] : make_float4(0,0,0,0);
                Kt[(d0 + d + 0) * KT_STR + col] = v.x;
                Kt[(d0 + d + 1) * KT_STR + col] = v.y;
                Kt[(d0 + d + 2) * KT_STR + col] = v.z;
                Kt[(d0 + d + 3) * KT_STR + col] = v.w;
            }
            int rr = tid >> 1, e0 = (tid & 1) * 16;
            int pv = g * GSZ + kc * 128 + rr;
            const float4* vsrc = (const float4*)&g_v[(long)(bN + pv) * 32];
            #pragma unroll
            for (int e = 0; e < 16; e += 4) {
                float4 v = (pv < N) ? vsrc[(e0 + e) >> 2] : make_float4(0,0,0,0);
                *(float4*)&Vs[rr * 32 + e0 + e] = v;
            }
        }
        __syncthreads();
        {   // stage A: sim 128x128 over K=128, 8x8 per thread via f32x2
            unsigned long long acc[8][4];
            #pragma unroll
            for (int a = 0; a < 8; a++)
                #pragma unroll
                for (int c = 0; c < 4; c++) acc[a][c] = 0ull;
            #pragma unroll 2
            for (int kk = 0; kk < 128; kk++) {
                unsigned long long kp[4];
                #pragma unroll
                for (int c = 0; c < 4; c++)
                    kp[c] = *(const unsigned long long*)&Kt[kk * KT_STR + tx*2 + c*32];
                #pragma unroll
                for (int a = 0; a < 8; a++) {
                    float qv = Qs[(a * 16 + ty) * QS_STR + kk];
                    unsigned long long qd = pk2(qv, qv);
                    #pragma unroll
                    for (int c = 0; c < 4; c++) fma2(acc[a][c], qd, kp[c]);
                }
            }
            int kbase = g * GSZ + kc * 128;
            #pragma unroll
            for (int a = 0; a < 8; a++) {
                int row = a * 16 + ty;
                #pragma unroll
                for (int c = 0; c < 4; c++) {
                    float2 f = up2(acc[a][c]);
                    int c0 = tx * 2 + c * 32;
                    float s0 = fmaxf(f.x * (1.0f/256.0f), 0.0f); s0 *= s0;
                    float s1 = fmaxf(f.y * (1.0f/256.0f), 0.0f); s1 *= s1;
                    if (kbase + c0     >= N) s0 = 0.0f;
                    if (kbase + c0 + 1 >= N) s1 = 0.0f;
                    *(unsigned long long*)&As[row * AS_STR + c0] = pk2(s0, s1);
                }
            }
        }
        __syncthreads();
        {   // stage B: O += A * V
            #pragma unroll 4
            for (int j = 0; j < 128; j++) {
                float aij = As[oi * AS_STR + j];
                unsigned long long ad = pk2(aij, aij);
                const ulonglong2* vp = (const ulonglong2*)&Vs[j * 32 + eh];
                ulonglong2 va = vp[0], vb = vp[1];
                fma2(oacc[0], ad, va.x); fma2(oacc[1], ad, va.y);
                fma2(oacc[2], ad, vb.x); fma2(oacc[3], ad, vb.y);
                ulonglong2 vc = vp[2], vd = vp[3];
                fma2(oacc[4], ad, vc.x); fma2(oacc[5], ad, vc.y);
                fma2(oacc[6], ad, vd.x); fma2(oacc[7], ad, vd.y);
            }
        }
    }
    int qpos = g * GSZ + qh * 128 + oi;
    if (qpos < N) {
        float* dst = &g_qo[(long)(bN + qpos) * 32 + eh];
        #pragma unroll
        for (int e = 0; e < 8; e++) {
            float2 f = up2(oacc[e]);
            *(float2*)&dst[e * 2] = f;
        }
    }
}

// ---------------- K3: linear attention KV partials (grid: 8 x B) ----------------
__global__ void k_linkvp() {
    __shared__ float slk[8][128];
    __shared__ float sv[8][32];
    int tid = threadIdx.x;
    int s = blockIdx.x, b = blockIdx.y;
    int bN = b * N;
    int p0 = s * 125, p1 = min(p0 + 125, N);
    unsigned long long acc[8];
    #pragma unroll
    for (int e = 0; e < 8; e++) acc[e] = 0ull;
    int dd = tid & 127, e0 = (tid >> 7) * 16;

    for (int pp = p0; pp < p1; pp += 8) {
        __syncthreads();
        {   int r = tid >> 5;
            int d4 = (tid & 31) * 4;
            int pos = pp + r;
            float4 v = (pos < p1) ? *(const float4*)&g_lk[(long)(bN + pos) * QKD + d4]
                                  : make_float4(0,0,0,0);
            *(float4*)&slk[r][d4] = v;
            int e = tid & 31;
            sv[r][e] = (pos < p1) ? g_v[(long)(bN + pos) * 32 + e] : 0.0f;
        }
        __syncthreads();
        #pragma unroll
        for (int r = 0; r < 8; r++) {
            float lv = slk[r][dd];
            unsigned long long ld = pk2(lv, lv);
            const ulonglong2* vp = (const ulonglong2*)&sv[r][e0];
            ulonglong2 va = vp[0], vb = vp[1], vc = vp[2], vd = vp[3];
            fma2(acc[0], ld, va.x); fma2(acc[1], ld, va.y);
            fma2(acc[2], ld, vb.x); fma2(acc[3], ld, vb.y);
            fma2(acc[4], ld, vc.x); fma2(acc[5], ld, vc.y);
            fma2(acc[6], ld, vd.x); fma2(acc[7], ld, vd.y);
        }
    }
    float* dst = &g_linkvp[((long)(b * 8 + s) * 128 + dd) * 32 + e0];
    #pragma unroll
    for (int e = 0; e < 8; e++) {
        float2 f = up2(acc[e]);
        *(float2*)&dst[e * 2] = f;
    }
}

// ---------------- K3b: reduce partials ----------------
__global__ void k_kvred() {
    int b = blockIdx.x, tid = threadIdx.x;
    for (int idx = tid; idx < 4096; idx += 256) {
        float s = 0.0f;
        #pragma unroll
        for (int k2 = 0; k2 < 8; k2++) s += g_linkvp[(long)(b * 8 + k2) * 4096 + idx];
        g_linkv[(long)b * 4096 + idx] = s * (1.0f / (float)N);
    }
}

// ---------------- K4: lin_out + gate + Wo + residual (grid: 12 x B) ----------------
__global__ void k_out(const float* __restrict__ Wo, const float* __restrict__ bo) {
    __shared__ float skv[4096];
    __shared__ float sWo[32*16];
    __shared__ float sbo[16];
    __shared__ float ovs[8][32];
    int tid = threadIdx.x;
    int b = blockIdx.y, ch = blockIdx.x;
    int bN = b * N;
    for (int i = tid; i < 1024; i += 256)
        ((float4*)skv)[i] = ((const float4*)&g_linkv[(long)b * 4096])[i];
    for (int i = tid; i < 512; i += 256) sWo[i] = Wo[i];
    if (tid < 16) sbo[tid] = bo[tid];
    __syncthreads();

    int w = tid >> 5, lane = tid & 31;
    int t0 = ch * 83, t1 = t0 + 83;   // 12*83 = 996 exactly
    for (int tok = t0 + w; tok < t1; tok += 8) {
        int tf = bN + tok;
        float4 lq4 = *(const float4*)&g_lq[(long)tf * QKD + lane * 4];
        float lqa[4] = {lq4.x, lq4.y, lq4.z, lq4.w};
        float acc = g_qo[(long)tf * 32 + lane];
        #pragma unroll
        for (int comp = 0; comp < 4; comp++) {
            #pragma unroll
            for (int src = 0; src < 32; src++) {
                float lv = __shfl_sync(0xffffffffu, lqa[comp], src);
                acc += lv * skv[(src * 4 + comp) * 32 + lane];
            }
        }
        acc *= g_gate[(long)tf * 32 + lane];
        ovs[w][lane] = acc;
        __syncwarp();
        if (lane < 16) {
            float y = sbo[lane];
            #pragma unroll
            for (int e = 0; e < 32; e++) y += ovs[w][e] * sWo[e * DIM + lane];
            g_x[(long)tf * DIM + lane] += y;
        }
        __syncwarp();
    }
}

// ---------------- K5: final norm + logits + vocab max ----------------
#define LOGITS_SMEM ((16*1024 + 1024 + 16*16) * 4)
__global__ void k_logits(const float* __restrict__ fg, const float* __restrict__ Wl,
                         const float* __restrict__ blv) {
    extern __shared__ float sm[];
    float* sW = sm;
    float* sb = sW + 16 * 1024;
    float* xn = sb + 1024;
    __shared__ float wred[8];
    __shared__ float xs[16];
    int tid = threadIdx.x;
    int base = blockIdx.x * 16;

    for (int i = tid; i < (16 * 1024) / 4; i += 256)
        ((float4*)sW)[i] = ((const float4*)Wl)[i];
    for (int i = tid; i < 1024; i += 256) sb[i] = blv[i];
    {   int tt = tid >> 4, d = tid & 15;
        xn[tt * 16 + d] = g_x[(long)(base + tt) * DIM + d];
    }
    __syncthreads();
    if (tid < 16) {
        float s = 0.0f;
        #pragma unroll
        for (int d = 0; d < 16; d++) { float v = xn[tid * 16 + d]; s += v * v; }
        xs[tid] = fg[0] / fmaxf(sqrtf(s) * 0.25f, 1e-5f);
    }
    __syncthreads();
    {   int tt = tid >> 4, d = tid & 15;
        xn[tt * 16 + d] *= xs[tt];
    }
    __syncthreads();
    int warp = tid >> 5, lane = tid & 31;
    int v0 = tid * 4;
    for (int tt = 0; tt < 16; tt++) {
        float s0 = sb[v0], s1 = sb[v0 + 1], s2 = sb[v0 + 2], s3 = sb[v0 + 3];
        #pragma unroll
        for (int d = 0; d < 16; d++) {
            float xv = xn[tt * 16 + d];
            float4 wv = *(const float4*)&sW[d * 1024 + v0];
            s0 += xv * wv.x; s1 += xv * wv.y; s2 += xv * wv.z; s3 += xv * wv.w;
        }
        float m = fmaxf(fmaxf(s0, s1), fmaxf(s2, s3));
        #pragma unroll
        for (int off = 16; off > 0; off >>= 1)
            m = fmaxf(m, __shfl_xor_sync(0xffffffff, m, off));
        if (lane == 0) wred[warp] = m;
        __syncthreads();
        if (tid == 0) {
            float mm = wred[0];
            #pragma unroll
            for (int j = 1; j < 8; j++) mm = fmaxf(mm, wred[j]);
            g_hmax[base + tt] = mm;
        }
        __syncthreads();
    }
}

// ---------------- K6: head MLP ----------------
__global__ void k_head(const float* __restrict__ W1, const float* __restrict__ b1,
                       const float* __restrict__ W2, const float* __restrict__ b2,
                       float* __restrict__ out) {
    __shared__ float red[8][32];
    __shared__ float rr[32];
    int tid = threadIdx.x;
    int b = blockIdx.x;
    int col = tid & 31, seg = tid >> 5;
    float acc = 0.0f;
    int t0 = seg * 125;
    int t1 = min(t0 + 125, N);
    for (int t = t0; t < t1; t++)
        acc += g_hmax[(long)b * N + t] * W1[t * 32 + col];
    red[seg][col] = acc;
    __syncthreads();
    if (tid < 32) {
        float s = b1[tid];
        #pragma unroll
        for (int k = 0; k < 8; k++) s += red[k][tid];
        rr[tid] = fmaxf(s, 0.0f);
    }
    __syncthreads();
    if (tid == 0) {
        float o = b2[0];
        #pragma unroll
        for (int j = 0; j < 32; j++) o += rr[j] * W2[j];
        out[b] = o;
    }
}

// ---------------- launch ----------------
extern "C" void kernel_launch(void* const* d_in, const int* in_sizes, int n_in,
                              void* d_out, int out_size) {
    const int*   kmer    = (const int*)  d_in[0];
    const float* emb     = (const float*)d_in[1];
    const float* psc     = (const float*)d_in[2];
    const float* norm_g  = (const float*)d_in[3];
    const float* Wh      = (const float*)d_in[4];
    const float* bh      = (const float*)d_in[5];
    const float* Wqk     = (const float*)d_in[6];
    const float* bqk     = (const float*)d_in[7];
    const float* gamma   = (const float*)d_in[8];
    const float* beta    = (const float*)d_in[9];
    const float* Wo      = (const float*)d_in[10];
    const float* bo      = (const float*)d_in[11];
    const float* fg      = (const float*)d_in[12];
    const float* Wl      = (const float*)d_in[13];
    const float* bl      = (const float*)d_in[14];
    const float* W1      = (const float*)d_in[15];
    const float* b1      = (const float*)d_in[16];
    const float* W2      = (const float*)d_in[17];
    const float* b2      = (const float*)d_in[18];
    float* out = (float*)d_out;

    cudaFuncSetAttribute(k_attn,   cudaFuncAttributeMaxDynamicSharedMemorySize, ATTN_SMEM);
    cudaFuncSetAttribute(k_logits, cudaFuncAttributeMaxDynamicSharedMemorySize, LOGITS_SMEM);

    k_embed<<<(BN * DIM + 255) / 256, 256>>>(kmer, emb, psc);
    k_rot<<<(N * 16 + 255) / 256, 256>>>();

    for (int l = 0; l < DEPTH; l++) {
        k_proj<<<BN / 16, 256>>>(norm_g + l,
                                 Wh + (long)l * 16 * 64, bh + (long)l * 64,
                                 Wqk + (long)l * 16 * 128, bqk + (long)l * 128,
                                 gamma + (long)l * 4 * QKD, beta + (long)l * 4 * QKD);
        k_attn<<<dim3(2, NG, B), 256, ATTN_SMEM>>>();
        k_linkvp<<<dim3(8, B), 256>>>();
        k_kvred<<<B, 256>>>();
        k_out<<<dim3(12, B), 256>>>(Wo + (long)l * 32 * DIM, bo + (long)l * DIM);
    }

    k_logits<<<BN / 16, 256, LOGITS_SMEM>>>(fg, Wl, bl);
    k_head<<<B, 256>>>(W1, b1, W2, b2, out);
    (void)in_sizes; (void)n_in; (void)out_size;
}